// round 1
// baseline (speedup 1.0000x reference)
#include <cuda_runtime.h>
#include <cuda_bf16.h>
#include <math.h>

// Problem constants
#define B    128          // batch
#define D    524288       // 512*32*32 features per sample
#define D4   (D/4)        // float4 count per sample = 131072
#define NC   12           // num classes
#define KT   128          // K-tile (floats) per CTA in pair-dot kernel
#define NPMAX 16384       // worst-case number of same-label (i<=j) pairs

// -------- device scratch (no allocation allowed) --------
__device__ float g_pd[NPMAX];     // pair dot accumulators
__device__ int   g_pairs[NPMAX];  // (i<<8)|j, i<=j, labels equal
__device__ int   g_npairs;
__device__ float g_w[B];          // normalized sample weights
__device__ int   g_members[B];    // sample indices sorted by class
__device__ int   g_start[NC + 1]; // class segment starts into g_members

// =====================================================================
// k0: prep — zero accumulators, enumerate same-label pairs, class lists
// =====================================================================
__global__ void k0_prep(const int* __restrict__ labels) {
    __shared__ int sl[B];
    __shared__ int sc[B];
    int t = threadIdx.x;
    sl[t] = labels[t];
    for (int p = t; p < NPMAX; p += B) g_pd[p] = 0.0f;
    __syncthreads();

    // count matches j >= t
    int c = 0;
    for (int j = t; j < B; ++j) c += (sl[j] == sl[t]);
    sc[t] = c;
    __syncthreads();

    if (t == 0) {
        // exclusive prefix over per-row pair counts
        int np = 0;
        for (int i = 0; i < B; ++i) { int v = sc[i]; sc[i] = np; np += v; }
        g_npairs = np;
        // class-sorted member list
        int cnt[NC];
        for (int cc = 0; cc < NC; ++cc) cnt[cc] = 0;
        for (int i = 0; i < B; ++i) cnt[sl[i]]++;
        int st = 0;
        for (int cc = 0; cc < NC; ++cc) { g_start[cc] = st; st += cnt[cc]; cnt[cc] = g_start[cc]; }
        g_start[NC] = st;
        for (int i = 0; i < B; ++i) g_members[cnt[sl[i]]++] = i;
    }
    __syncthreads();

    // fill this row's pairs at its offset
    int off = sc[t];
    for (int j = t; j < B; ++j)
        if (sl[j] == sl[t]) g_pairs[off++] = (t << 8) | j;
}

// =====================================================================
// k1: masked pairwise dots, split-K. Each CTA stages a 128 x KT fp32
// tile of all rows in SMEM, then warps sweep the same-label pair list
// computing partial dots, reduced via shfl, one atomicAdd per pair/CTA.
// =====================================================================
__global__ void __launch_bounds__(256) k1_pairdots(const float* __restrict__ features) {
    extern __shared__ float smem[];            // [B][KT]
    const int tid  = threadIdx.x;
    const int wid  = tid >> 5;
    const int lane = tid & 31;

    // ---- load tile: 128 rows x KT floats, as float4 ----
    const int c4_per_row = KT / 4;             // 32
    const float4* F4 = (const float4*)features;
    float4* S4 = (float4*)smem;
    const int k0_4 = blockIdx.x * c4_per_row;  // float4 offset of this K-chunk
    for (int idx = tid; idx < B * c4_per_row; idx += 256) {
        int r = idx >> 5;                      // idx / 32
        int c = idx & 31;
        S4[r * c4_per_row + c] = F4[(size_t)r * D4 + k0_4 + c];
    }
    __syncthreads();

    // ---- pair sweep: warp per pair ----
    const int P = g_npairs;
    for (int p = wid; p < P; p += 8) {
        int pr = g_pairs[p];
        int i = pr >> 8, j = pr & 255;
        float4 a = S4[i * c4_per_row + lane];
        float4 b = S4[j * c4_per_row + lane];
        float s = a.x * b.x + a.y * b.y + a.z * b.z + a.w * b.w;
        #pragma unroll
        for (int o = 16; o > 0; o >>= 1) s += __shfl_down_sync(0xFFFFFFFFu, s, o);
        if (lane == 0) atomicAdd(&g_pd[p], s);
    }
}

// =====================================================================
// k2: distances -> dsum -> smoothed normalized weights (tiny)
// =====================================================================
__global__ void k2_weights() {
    __shared__ float sdiag[B];
    __shared__ float swv[B];
    __shared__ float ssum;
    int i = threadIdx.x;
    int P = g_npairs;

    // pick up this row's self-dot (diagonal pair always exists)
    for (int p = 0; p < P; ++p) {
        int pr = g_pairs[p];
        if (pr == ((i << 8) | i)) sdiag[i] = g_pd[p];
    }
    __syncthreads();

    float dsum = 0.0f;
    for (int p = 0; p < P; ++p) {
        int pr = g_pairs[p];
        int a = pr >> 8, b = pr & 255;
        if (a == b) continue;
        if (a == i || b == i) {
            int j = (a == i) ? b : a;
            float d2 = sdiag[i] + sdiag[j] - 2.0f * g_pd[p];
            dsum += (d2 > 0.0f) ? sqrtf(d2) : 0.0f;
        }
    }
    float w = 1.0f / (sqrtf(dsum * dsum + 25.0f) + 1e-12f);
    swv[i] = w;
    __syncthreads();
    if (i == 0) {
        float S = 0.0f;
        for (int t = 0; t < B; ++t) S += swv[t];
        ssum = S;
    }
    __syncthreads();
    g_w[i] = w / (ssum + 1e-12f);
}

// =====================================================================
// k3: label-grouped weighted scatter-sum. One thread per float4 column;
// iterate classes in member-sorted order so each feature element is
// read exactly once and every output element (incl. empty classes) is
// written.
// =====================================================================
__global__ void __launch_bounds__(256) k3_scatter(const float* __restrict__ features,
                                                 float* __restrict__ out) {
    __shared__ float sw[B];
    __shared__ int   sm[B];
    __shared__ int   sst[NC + 1];
    int t = threadIdx.x;
    if (t < B)      { sw[t] = g_w[t]; sm[t] = g_members[t]; }
    if (t < NC + 1) { sst[t] = g_start[t]; }
    __syncthreads();

    const size_t t4 = (size_t)blockIdx.x * 256 + t;   // 0 .. D4-1
    const float4* F4 = (const float4*)features;
    float4* O4 = (float4*)out;

    for (int c = 0; c < NC; ++c) {
        float4 acc = make_float4(0.f, 0.f, 0.f, 0.f);
        int e = sst[c + 1];
        #pragma unroll 4
        for (int s = sst[c]; s < e; ++s) {
            int m = sm[s];
            float wm = sw[m];
            float4 v = F4[(size_t)m * D4 + t4];
            acc.x += wm * v.x;
            acc.y += wm * v.y;
            acc.z += wm * v.z;
            acc.w += wm * v.w;
        }
        O4[(size_t)c * D4 + t4] = acc;
    }
}

// =====================================================================
extern "C" void kernel_launch(void* const* d_in, const int* in_sizes, int n_in,
                              void* d_out, int out_size) {
    const float* features;
    const int*   labels;
    if (in_sizes[0] == B) {   // defensive vs metadata ordering
        labels   = (const int*)d_in[0];
        features = (const float*)d_in[1];
    } else {
        features = (const float*)d_in[0];
        labels   = (const int*)d_in[1];
    }
    float* out = (float*)d_out;

    // opt-in to 64 KB dynamic SMEM for k1 (idempotent; ignore errors, e.g.
    // if called during graph capture — the attribute persists from the
    // first, non-captured call)
    (void)cudaFuncSetAttribute((const void*)k1_pairdots,
                               cudaFuncAttributeMaxDynamicSharedMemorySize,
                               B * KT * (int)sizeof(float));

    k0_prep<<<1, B>>>(labels);
    k1_pairdots<<<D / KT, 256, B * KT * sizeof(float)>>>(features);
    k2_weights<<<1, B>>>();
    k3_scatter<<<D4 / 256, 256>>>(features, out);
}

// round 2
// speedup vs baseline: 1.8228x; 1.8228x over previous
#include <cuda_runtime.h>
#include <cuda_bf16.h>
#include <math.h>

#define B     128
#define D     524288           // 512*32*32
#define D4    (D/4)            // 131072 float4 per row
#define NC    12
#define KT4   64               // float4 per row per k1 chunk (256 floats)
#define NCHUNK (D4/KT4)        // 2048 chunks
#define K1_THREADS 512
#define K1_WARPS   (K1_THREADS/32)

// -------- device scratch (no allocation allowed) --------
__device__ float g_pd[B * B];     // pair dots, slot-indexed [s][b], s<=b same class
__device__ float g_wslot[B];      // normalized weights, slot-ordered
__device__ int   g_members[B];    // slot -> sample index (class-sorted)
__device__ int   g_start[NC + 1]; // class segment starts (slots)
__device__ int   g_send[B];       // slot -> end slot of its class

// =====================================================================
// k0: zero pd, build class-sorted slot tables
// =====================================================================
__global__ void k0_prep(const int* __restrict__ labels) {
    __shared__ int sl[B];
    int t = threadIdx.x;
    sl[t] = labels[t];
    for (int p = t; p < B * B; p += B) g_pd[p] = 0.0f;
    __syncthreads();
    if (t == 0) {
        int cnt[NC];
        for (int c = 0; c < NC; ++c) cnt[c] = 0;
        for (int i = 0; i < B; ++i) cnt[sl[i]]++;
        int st = 0;
        for (int c = 0; c < NC; ++c) { g_start[c] = st; st += cnt[c]; cnt[c] = g_start[c]; }
        g_start[NC] = st;
        for (int i = 0; i < B; ++i) {
            int c = sl[i];
            int slot = cnt[c]++;
            g_members[slot] = i;
        }
        for (int c = 0; c < NC; ++c)
            for (int s = g_start[c]; s < g_start[c + 1]; ++s)
                g_send[s] = g_start[c + 1];
    }
}

// =====================================================================
// k1: masked pair dots. One CTA per 256-float K-chunk. Stage all 128
// rows (slot-ordered) in SMEM (128KB). Warp owns a row-slot: caches its
// 2 float4 in registers, sweeps same-class partners b >= s from SMEM,
// per-lane dot -> shfl reduce -> one atomicAdd per (pair, chunk).
// =====================================================================
__global__ void __launch_bounds__(K1_THREADS, 1)
k1_pairdots(const float* __restrict__ features) {
    extern __shared__ float4 S[];              // [B][KT4]
    __shared__ int sm_m[B];
    __shared__ int sm_end[B];

    const int tid  = threadIdx.x;
    const int wid  = tid >> 5;
    const int lane = tid & 31;

    if (tid < B) { sm_m[tid] = g_members[tid]; sm_end[tid] = g_send[tid]; }
    __syncthreads();

    // ---- stage tile: 128 rows x 64 float4, coalesced 1KB runs ----
    const float4* F4 = (const float4*)features;
    const int k0_4 = blockIdx.x * KT4;
    for (int idx = tid; idx < B * KT4; idx += K1_THREADS) {
        int r = idx >> 6;                      // /KT4
        int c = idx & (KT4 - 1);
        S[idx] = F4[(size_t)sm_m[r] * D4 + k0_4 + c];
    }
    __syncthreads();

    // ---- row-task sweep ----
    for (int s = wid; s < B; s += K1_WARPS) {
        const int e = sm_end[s];
        // register-cache this row's chunk (2 float4 per lane)
        float4 a0 = S[s * KT4 + lane];
        float4 a1 = S[s * KT4 + 32 + lane];
        #pragma unroll 2
        for (int b = s; b < e; ++b) {
            float4 b0 = S[b * KT4 + lane];
            float4 b1 = S[b * KT4 + 32 + lane];
            float p = a0.x * b0.x + a0.y * b0.y + a0.z * b0.z + a0.w * b0.w
                    + a1.x * b1.x + a1.y * b1.y + a1.z * b1.z + a1.w * b1.w;
            #pragma unroll
            for (int o = 16; o > 0; o >>= 1) p += __shfl_down_sync(0xFFFFFFFFu, p, o);
            if (lane == 0) atomicAdd(&g_pd[s * B + b], p);
        }
    }
}

// =====================================================================
// k2: distances -> dsum -> smoothed normalized weights (slot-ordered)
// =====================================================================
__global__ void k2_weights() {
    __shared__ float sdiag[B];
    __shared__ float swv[B];
    __shared__ float ssum;
    __shared__ int sst[NC + 1];
    int s = threadIdx.x;
    if (s < NC + 1) sst[s] = g_start[s];
    sdiag[s] = g_pd[s * B + s];
    __syncthreads();

    // find class bounds for this slot
    int st = 0, en = 0;
    for (int c = 0; c < NC; ++c)
        if (s >= sst[c] && s < sst[c + 1]) { st = sst[c]; en = sst[c + 1]; }

    float dsum = 0.0f;
    for (int b = st; b < en; ++b) {
        if (b == s) continue;
        float pd = (b >= s) ? g_pd[s * B + b] : g_pd[b * B + s];
        float d2 = sdiag[s] + sdiag[b] - 2.0f * pd;
        dsum += (d2 > 0.0f) ? sqrtf(d2) : 0.0f;
    }
    float w = 1.0f / (sqrtf(dsum * dsum + 25.0f) + 1e-12f);
    swv[s] = w;
    __syncthreads();
    if (s == 0) {
        float S = 0.0f;
        for (int t = 0; t < B; ++t) S += swv[t];
        ssum = S;
    }
    __syncthreads();
    g_wslot[s] = w / (ssum + 1e-12f);
}

// =====================================================================
// k3: weighted class scatter-sum, single rolling pass over the slot-
// sorted member list with an 8-deep prefetch ring (MLP=8). One float4
// accumulator, flushed at class boundaries (handles empty classes).
// =====================================================================
#define PF 8
__global__ void __launch_bounds__(256) k3_scatter(const float* __restrict__ features,
                                                  float* __restrict__ out) {
    __shared__ float sw[B];
    __shared__ int   sm[B];
    __shared__ int   sst[NC + 1];
    int t = threadIdx.x;
    if (t < B)      { sw[t] = g_wslot[t]; sm[t] = g_members[t]; }
    if (t < NC + 1) { sst[t] = g_start[t]; }
    __syncthreads();

    const size_t t4 = (size_t)blockIdx.x * 256 + t;
    const float4* F4 = (const float4*)features;
    float4* O4 = (float4*)out;

    float4 buf[PF];
    #pragma unroll
    for (int k = 0; k < PF; ++k)
        buf[k] = F4[(size_t)sm[k] * D4 + t4];

    int c = 0;
    int nb = sst[1];
    float4 acc = make_float4(0.f, 0.f, 0.f, 0.f);

    for (int s0 = 0; s0 < B; s0 += PF) {
        #pragma unroll
        for (int k = 0; k < PF; ++k) {
            int s = s0 + k;
            while (s == nb && c < NC) {           // class boundary (incl. empty)
                O4[(size_t)c * D4 + t4] = acc;
                acc = make_float4(0.f, 0.f, 0.f, 0.f);
                ++c;
                nb = sst[c + 1];
            }
            float4 v = buf[k];
            float w = sw[s];
            acc.x += w * v.x; acc.y += w * v.y;
            acc.z += w * v.z; acc.w += w * v.w;
            int sp = s + PF;
            if (sp < B) buf[k] = F4[(size_t)sm[sp] * D4 + t4];
        }
    }
    while (c < NC) {                               // trailing flush
        O4[(size_t)c * D4 + t4] = acc;
        acc = make_float4(0.f, 0.f, 0.f, 0.f);
        ++c;
    }
}

// =====================================================================
extern "C" void kernel_launch(void* const* d_in, const int* in_sizes, int n_in,
                              void* d_out, int out_size) {
    const float* features;
    const int*   labels;
    if (in_sizes[0] == B) {
        labels   = (const int*)d_in[0];
        features = (const float*)d_in[1];
    } else {
        features = (const float*)d_in[0];
        labels   = (const int*)d_in[1];
    }
    float* out = (float*)d_out;

    const int k1_smem = B * KT4 * (int)sizeof(float4);   // 128 KB
    (void)cudaFuncSetAttribute((const void*)k1_pairdots,
                               cudaFuncAttributeMaxDynamicSharedMemorySize,
                               k1_smem);

    k0_prep<<<1, B>>>(labels);
    k1_pairdots<<<NCHUNK, K1_THREADS, k1_smem>>>(features);
    k2_weights<<<1, B>>>();
    k3_scatter<<<D4 / 256, 256>>>(features, out);
}